// round 7
// baseline (speedup 1.0000x reference)
#include <cuda_runtime.h>
#include <cuda_fp16.h>
#include <cstdint>

#define TE 128
#define NT 256

// Transposed f16 weights [n][k]. Static scratch, no runtime alloc.
__device__ __half g_W1T[256 * 512];
__device__ __half g_W2T[128 * 256];

// ---------------- helpers ----------------
__device__ __forceinline__ uint32_t smem_u32(const void* p) {
    uint32_t a;
    asm("{ .reg .u64 t; cvta.to.shared.u64 t, %1; cvt.u32.u64 %0, t; }" : "=r"(a) : "l"(p));
    return a;
}
__device__ __forceinline__ uint32_t f2h2(float lo, float hi) {
    uint32_t r;
    asm("cvt.rn.f16x2.f32 %0, %1, %2;" : "=r"(r) : "f"(hi), "f"(lo));
    return r;
}
#define CP_ASYNC16(dst_u32, src_ptr) \
    asm volatile("cp.async.cg.shared.global [%0], [%1], 16;" :: "r"(dst_u32), "l"(src_ptr) : "memory")
#define CP_COMMIT() asm volatile("cp.async.commit_group;" ::: "memory")
#define CP_WAIT(n)  asm volatile("cp.async.wait_group %0;" :: "n"(n) : "memory")

__device__ __forceinline__ void mma16(float* c, const uint32_t* a, uint32_t b0, uint32_t b1) {
    asm volatile(
        "mma.sync.aligned.m16n8k16.row.col.f32.f16.f16.f32 "
        "{%0,%1,%2,%3}, {%4,%5,%6,%7}, {%8,%9}, {%0,%1,%2,%3};"
        : "+f"(c[0]), "+f"(c[1]), "+f"(c[2]), "+f"(c[3])
        : "r"(a[0]), "r"(a[1]), "r"(a[2]), "r"(a[3]), "r"(b0), "r"(b1));
}
__device__ __forceinline__ void ldm4(uint32_t* r, uint32_t addr) {
    asm volatile("ldmatrix.sync.aligned.m8n8.x4.shared.b16 {%0,%1,%2,%3}, [%4];"
                 : "=r"(r[0]), "=r"(r[1]), "=r"(r[2]), "=r"(r[3]) : "r"(addr));
}

// ---------------- smem layout (BYTE offsets) ----------------
#define STRA     1040                 // A row stride (512 f16 + pad): 4-bank row stagger
#define STRX     528                  // x1 row stride (256 f16 + pad)
#define RSTR     80                   // ring row stride (32 f16 + pad)
#define OFF_A    0                    // [128][STRA]        133,120 B
#define OFF_X1   133120               // [128][STRX]         67,584 B
#define OFF_RING 200704               // 2 x 128 x RSTR      20,480 B
#define RBUF     10240
#define OFF_B1   221184               // 256 f32
#define OFF_B2   222208               // 128 f32
#define OFF_W3   222720               // 256 f32
#define OFF_B3   223744               // 2 f32
#define SMEM_BYTES 223760

// ---------------- prep: transpose + single-RN-round to f16 ----------------
__global__ void prep_kernel(const float* __restrict__ W1, const float* __restrict__ W2) {
    int i = blockIdx.x * blockDim.x + threadIdx.x;
    if (i < 256 * 512) {
        int n = i >> 9, k = i & 511;
        g_W1T[i] = __float2half_rn(W1[k * 256 + n]);
    } else {
        int j = i - 256 * 512;
        if (j < 128 * 256) {
            int n = j >> 8, k = j & 255;
            g_W2T[j] = __float2half_rn(W2[k * 128 + n]);
        }
    }
}

// ---------------- ring fill: one 128n x 32k chunk (512 x 16B) ----------------
__device__ __forceinline__ void issue_w(uint32_t smb, int tid, const __half* gsrc,
                                        int kstride, int c, int d) {
    #pragma unroll
    for (int i = 0; i < 2; i++) {
        int idx = tid + i * NT;           // 0..511
        int n = idx >> 2, q = idx & 3;
        const __half* s = gsrc + (size_t)n * kstride + c * 32 + q * 8;
        CP_ASYNC16(smb + OFF_RING + d * RBUF + n * RSTR + q * 16, s);
    }
}
// flat chunk schedule: 0-15 L1 half0, 16-31 L1 half1, 32-39 L2
__device__ __forceinline__ void issue_chunk(uint32_t smb, int tid, int gi) {
    int d = gi & 1;
    if (gi < 32) issue_w(smb, tid, g_W1T + (size_t)(gi >> 4) * 128 * 512, 512, gi & 15, d);
    else         issue_w(smb, tid, g_W2T, 256, gi - 32, d);
}

// ---------------- main fused MLP ----------------
__global__ __launch_bounds__(NT, 1)
void edge_mlp_ldm(const float* __restrict__ node,
                  const int*   __restrict__ src,
                  const int*   __restrict__ dst,
                  const float* __restrict__ b1,
                  const float* __restrict__ b2,
                  const float* __restrict__ W3,
                  const float* __restrict__ b3,
                  float* __restrict__ out, int E)
{
    extern __shared__ char smc[];
    const uint32_t smb = smem_u32(smc);
    float* smf = (float*)smc;

    const int tid = threadIdx.x;
    const int lane = tid & 31;
    const int g = lane >> 2, t = lane & 3;
    const int wid = tid >> 5;
    const int wm = wid >> 2, wn = wid & 3;      // warp grid 2(M) x 4(N)
    const int e0 = blockIdx.x * TE;
    const int nedge = min(TE, E - e0);

    issue_chunk(smb, tid, 0);
    CP_COMMIT();

    // ---- build A = f16 edge_input [128][512] (one rounding per element) ----
    #pragma unroll 4
    for (int i = 0; i < 16; i++) {
        int idx = tid + i * NT;
        int m = idx >> 5, c4 = idx & 31;
        int e = min(e0 + m, E - 1);
        int si = src[e], di = dst[e];
        float4 vi = ((const float4*)node)[(size_t)si * 32 + c4];
        float4 vj = ((const float4*)node)[(size_t)di * 32 + c4];
        char* row = smc + OFF_A + m * STRA + c4 * 8;
        *(uint2*)(row +   0) = make_uint2(f2h2(vi.x, vi.y), f2h2(vi.z, vi.w));
        *(uint2*)(row + 256) = make_uint2(f2h2(vj.x, vj.y), f2h2(vj.z, vj.w));
        *(uint2*)(row + 512) = make_uint2(f2h2(fabsf(vi.x - vj.x), fabsf(vi.y - vj.y)),
                                          f2h2(fabsf(vi.z - vj.z), fabsf(vi.w - vj.w)));
        *(uint2*)(row + 768) = make_uint2(f2h2(vi.x * vj.x, vi.y * vj.y),
                                          f2h2(vi.z * vj.z, vi.w * vj.w));
    }
    for (int i = tid; i < 256; i += NT) smf[OFF_B1 / 4 + i] = b1[i];
    for (int i = tid; i < 128; i += NT) smf[OFF_B2 / 4 + i] = b2[i];
    for (int i = tid; i < 256; i += NT) smf[OFF_W3 / 4 + i] = W3[i];
    if (tid < 2) smf[OFF_B3 / 4 + tid] = b3[tid];
    __syncthreads();

    // ---- per-lane ldmatrix address bases ----
    const int aRow = lane & 15;
    const int aKoff = (lane >> 4) << 3;                 // 0 or 8 (f16)
    const uint32_t aBase = smb + OFF_A  + (wm * 64 + aRow) * STRA + aKoff * 2;
    const uint32_t xBase = smb + OFF_X1 + (wm * 64 + aRow) * STRX + aKoff * 2;
    const int nl = ((lane >> 4) << 3) + (lane & 7);
    const int bKoff = (lane & 8) ? 8 : 0;
    const uint32_t bBase = smb + OFF_RING + (wn * 32 + nl) * RSTR + bKoff * 2;

    // layer-2 accumulators (persist), init with b2
    float accL2[64];
    #pragma unroll
    for (int mt = 0; mt < 4; mt++)
        #pragma unroll
        for (int nt = 0; nt < 4; nt++) {
            int col = wn * 32 + nt * 8 + 2 * t;
            float v0 = smf[OFF_B2 / 4 + col], v1 = smf[OFF_B2 / 4 + col + 1];
            float* A = &accL2[(mt * 4 + nt) * 4];
            A[0] = v0; A[1] = v1; A[2] = v0; A[3] = v1;
        }

    int gi = 0;
    // ================= layer 1 (two n-halves) =================
    for (int h = 0; h < 2; h++) {
        float accL1[64];
        #pragma unroll
        for (int mt = 0; mt < 4; mt++)
            #pragma unroll
            for (int nt = 0; nt < 4; nt++) {
                int col = h * 128 + wn * 32 + nt * 8 + 2 * t;
                float v0 = smf[OFF_B1 / 4 + col], v1 = smf[OFF_B1 / 4 + col + 1];
                float* A = &accL1[(mt * 4 + nt) * 4];
                A[0] = v0; A[1] = v1; A[2] = v0; A[3] = v1;
            }

        for (int c = 0; c < 16; c++, gi++) {
            if (gi < 39) { issue_chunk(smb, tid, gi + 1); CP_COMMIT(); CP_WAIT(1); }
            else         { CP_WAIT(0); }
            __syncthreads();
            const int d = gi & 1;

            #pragma unroll
            for (int kt = 0; kt < 2; kt++) {
                uint32_t aF[4][4];
                #pragma unroll
                for (int mt = 0; mt < 4; mt++)
                    ldm4(aF[mt], aBase + mt * (16 * STRA) + (c * 32 + kt * 16) * 2);
                uint32_t bF[2][4];
                #pragma unroll
                for (int np = 0; np < 2; np++)
                    ldm4(bF[np], bBase + d * RBUF + np * (16 * RSTR) + kt * 32);
                #pragma unroll
                for (int mt = 0; mt < 4; mt++) {
                    mma16(&accL1[(mt * 4 + 0) * 4], aF[mt], bF[0][0], bF[0][1]);
                    mma16(&accL1[(mt * 4 + 1) * 4], aF[mt], bF[0][2], bF[0][3]);
                    mma16(&accL1[(mt * 4 + 2) * 4], aF[mt], bF[1][0], bF[1][1]);
                    mma16(&accL1[(mt * 4 + 3) * 4], aF[mt], bF[1][2], bF[1][3]);
                }
            }
            __syncthreads();
        }

        // x1 = f16x2(relu(acc)) -> smem (conflict-free: bank = 4g + t + const)
        #pragma unroll
        for (int mt = 0; mt < 4; mt++) {
            int r = wm * 64 + mt * 16 + g;
            #pragma unroll
            for (int nt = 0; nt < 4; nt++) {
                int col = h * 128 + wn * 32 + nt * 8 + 2 * t;
                float* A = &accL1[(mt * 4 + nt) * 4];
                *(uint32_t*)(smc + OFF_X1 + r * STRX + col * 2) =
                    f2h2(fmaxf(A[0], 0.f), fmaxf(A[1], 0.f));
                *(uint32_t*)(smc + OFF_X1 + (r + 8) * STRX + col * 2) =
                    f2h2(fmaxf(A[2], 0.f), fmaxf(A[3], 0.f));
            }
        }
    }

    // ================= layer 2 (K=256, 8 chunks) =================
    for (int c = 0; c < 8; c++, gi++) {
        if (gi < 39) { issue_chunk(smb, tid, gi + 1); CP_COMMIT(); CP_WAIT(1); }
        else         { CP_WAIT(0); }
        __syncthreads();   // also orders x1 stores before reads
        const int d = gi & 1;

        #pragma unroll
        for (int kt = 0; kt < 2; kt++) {
            uint32_t aF[4][4];
            #pragma unroll
            for (int mt = 0; mt < 4; mt++)
                ldm4(aF[mt], xBase + mt * (16 * STRX) + (c * 32 + kt * 16) * 2);
            uint32_t bF[2][4];
            #pragma unroll
            for (int np = 0; np < 2; np++)
                ldm4(bF[np], bBase + d * RBUF + np * (16 * RSTR) + kt * 32);
            #pragma unroll
            for (int mt = 0; mt < 4; mt++) {
                mma16(&accL2[(mt * 4 + 0) * 4], aF[mt], bF[0][0], bF[0][1]);
                mma16(&accL2[(mt * 4 + 1) * 4], aF[mt], bF[0][2], bF[0][3]);
                mma16(&accL2[(mt * 4 + 2) * 4], aF[mt], bF[1][0], bF[1][1]);
                mma16(&accL2[(mt * 4 + 3) * 4], aF[mt], bF[1][2], bF[1][3]);
            }
        }
        __syncthreads();
    }

    // ================= layer 3: register relu.W3 + quad shuffle-reduce =================
    float* s_red = (float*)(smc + OFF_RING);   // ring is dead
    #pragma unroll
    for (int mt = 0; mt < 4; mt++) {
        int r = wm * 64 + mt * 16 + g;
        float p00 = 0.f, p01 = 0.f, p10 = 0.f, p11 = 0.f;
        #pragma unroll
        for (int nt = 0; nt < 4; nt++) {
            float* A = &accL2[(mt * 4 + nt) * 4];
            int col = wn * 32 + nt * 8 + 2 * t;
            float w00 = smf[OFF_W3 / 4 + 2 * col],     w01 = smf[OFF_W3 / 4 + 2 * col + 1];
            float w10 = smf[OFF_W3 / 4 + 2 * col + 2], w11 = smf[OFF_W3 / 4 + 2 * col + 3];
            float x0 = fmaxf(A[0], 0.f), x1v = fmaxf(A[1], 0.f);
            float x2v = fmaxf(A[2], 0.f), x3v = fmaxf(A[3], 0.f);
            p00 += x0 * w00 + x1v * w10;
            p01 += x0 * w01 + x1v * w11;
            p10 += x2v * w00 + x3v * w10;
            p11 += x2v * w01 + x3v * w11;
        }
        p00 += __shfl_xor_sync(0xFFFFFFFFu, p00, 1);
        p00 += __shfl_xor_sync(0xFFFFFFFFu, p00, 2);
        p01 += __shfl_xor_sync(0xFFFFFFFFu, p01, 1);
        p01 += __shfl_xor_sync(0xFFFFFFFFu, p01, 2);
        p10 += __shfl_xor_sync(0xFFFFFFFFu, p10, 1);
        p10 += __shfl_xor_sync(0xFFFFFFFFu, p10, 2);
        p11 += __shfl_xor_sync(0xFFFFFFFFu, p11, 1);
        p11 += __shfl_xor_sync(0xFFFFFFFFu, p11, 2);
        if (t == 0) {
            s_red[r * 8 + wn * 2 + 0] = p00;
            s_red[r * 8 + wn * 2 + 1] = p01;
            s_red[(r + 8) * 8 + wn * 2 + 0] = p10;
            s_red[(r + 8) * 8 + wn * 2 + 1] = p11;
        }
    }
    __syncthreads();

    {
        int row = tid >> 1, cc = tid & 1;
        float sum = smf[OFF_B3 / 4 + cc]
                  + s_red[row * 8 + 0 + cc] + s_red[row * 8 + 2 + cc]
                  + s_red[row * 8 + 4 + cc] + s_red[row * 8 + 6 + cc];
        if (row < nedge) out[(size_t)(e0 + row) * 2 + cc] = sum;
    }
}

extern "C" void kernel_launch(void* const* d_in, const int* in_sizes, int n_in,
                              void* d_out, int out_size)
{
    const float* node = (const float*)d_in[0];
    const int*   src  = (const int*)  d_in[1];
    const int*   dst  = (const int*)  d_in[2];
    const float* W1   = (const float*)d_in[3];
    const float* b1   = (const float*)d_in[4];
    const float* W2   = (const float*)d_in[5];
    const float* b2   = (const float*)d_in[6];
    const float* W3   = (const float*)d_in[7];
    const float* b3   = (const float*)d_in[8];
    float* out = (float*)d_out;

    const int E = in_sizes[1];

    {
        int total = 256 * 512 + 128 * 256;
        prep_kernel<<<(total + 255) / 256, 256>>>(W1, W2);
    }

    cudaFuncSetAttribute(edge_mlp_ldm,
                         cudaFuncAttributeMaxDynamicSharedMemorySize, SMEM_BYTES);

    const int grid = (E + TE - 1) / TE;
    edge_mlp_ldm<<<grid, NT, SMEM_BYTES>>>(node, src, dst, b1, b2, W3, b3, out, E);
}

// round 8
// speedup vs baseline: 1.0005x; 1.0005x over previous
#include <cuda_runtime.h>
#include <cuda_fp16.h>
#include <cstdint>

#define TE 64
#define NT 256

// Transposed f16 weights [n][k]. Static scratch, no runtime alloc.
__device__ __half g_W1T[256 * 512];
__device__ __half g_W2T[128 * 256];

// ---------------- helpers ----------------
__device__ __forceinline__ uint32_t smem_u32(const void* p) {
    uint32_t a;
    asm("{ .reg .u64 t; cvta.to.shared.u64 t, %1; cvt.u32.u64 %0, t; }" : "=r"(a) : "l"(p));
    return a;
}
__device__ __forceinline__ uint32_t f2h2(float lo, float hi) {
    uint32_t r;
    asm("cvt.rn.f16x2.f32 %0, %1, %2;" : "=r"(r) : "f"(hi), "f"(lo));
    return r;
}
#define CP_ASYNC16(dst_u32, src_ptr) \
    asm volatile("cp.async.cg.shared.global [%0], [%1], 16;" :: "r"(dst_u32), "l"(src_ptr) : "memory")
#define CP_COMMIT() asm volatile("cp.async.commit_group;" ::: "memory")
#define CP_WAIT(n)  asm volatile("cp.async.wait_group %0;" :: "n"(n) : "memory")

__device__ __forceinline__ void mma16(float* c, const uint32_t* a, uint32_t b0, uint32_t b1) {
    asm volatile(
        "mma.sync.aligned.m16n8k16.row.col.f32.f16.f16.f32 "
        "{%0,%1,%2,%3}, {%4,%5,%6,%7}, {%8,%9}, {%0,%1,%2,%3};"
        : "+f"(c[0]), "+f"(c[1]), "+f"(c[2]), "+f"(c[3])
        : "r"(a[0]), "r"(a[1]), "r"(a[2]), "r"(a[3]), "r"(b0), "r"(b1));
}
__device__ __forceinline__ void ldm4(uint32_t* r, uint32_t addr) {
    asm volatile("ldmatrix.sync.aligned.m8n8.x4.shared.b16 {%0,%1,%2,%3}, [%4];"
                 : "=r"(r[0]), "=r"(r[1]), "=r"(r[2]), "=r"(r[3]) : "r"(addr));
}
// derive |a-b| and a*b fragments in f16x2 registers
__device__ __forceinline__ uint32_t habs_sub2(uint32_t a, uint32_t b) {
    __half2 r = __habs2(__hsub2(*(__half2*)&a, *(__half2*)&b));
    return *(uint32_t*)&r;
}
__device__ __forceinline__ uint32_t hmul2u(uint32_t a, uint32_t b) {
    __half2 r = __hmul2(*(__half2*)&a, *(__half2*)&b);
    return *(uint32_t*)&r;
}

// ---------------- smem layout (BYTE offsets) ----------------
#define STRH     272                // hi/hj row stride (128 f16 + 16B pad), 16B-aligned
#define STRX     528                // x1 row stride (256 f16 + 16B pad)
#define RS1      48                 // L1 ring row stride (16 f16 + pad)
#define RS2      80                 // L2 ring row stride (32 f16 + pad)
#define RSLOT    12288              // ring slot: max(2*128*48, 128*80)
#define OFF_HI   0                  // [64][STRH]   17,408
#define OFF_HJ   17408              // [64][STRH]   17,408
#define OFF_X1   34816              // [64][STRX]   33,792
#define OFF_RING 68608              // 2 x RSLOT    24,576
#define OFF_B1   93184              // 256 f32
#define OFF_B2   94208              // 128 f32
#define OFF_W3   94720              // 256 f32
#define OFF_B3   95744              // 2 f32
#define SMEM_BYTES 95760

// ---------------- prep: transpose + single-RN-round to f16 ----------------
__global__ void prep_kernel(const float* __restrict__ W1, const float* __restrict__ W2) {
    int i = blockIdx.x * blockDim.x + threadIdx.x;
    if (i < 256 * 512) {
        int n = i >> 9, k = i & 511;
        g_W1T[i] = __float2half_rn(W1[k * 256 + n]);
    } else {
        int j = i - 256 * 512;
        if (j < 128 * 256) {
            int n = j >> 8, k = j & 255;
            g_W2T[j] = __float2half_rn(W2[k * 128 + n]);
        }
    }
}

// ---------------- ring fill (512 x 16B per chunk = 2 cp.async/thread) ----------------
// gi 0..31: L1  (h = gi>>4, sub = gi&15: c = sub>>1 k-window of 16, p = sub&1 seg-pair)
//           slot = [2 seg'][128 n][RS1], rows are W1T[h*128+n][(2p+s')*128 + c*16 + ..]
// gi 32..39: L2 (c = gi-32 k-window of 32) slot = [128 n][RS2]
__device__ __forceinline__ void issue_chunk(uint32_t smb, int tid, int gi) {
    const int d = gi & 1;
    if (gi < 32) {
        const int h = gi >> 4, sub = gi & 15, c = sub >> 1, p = sub & 1;
        #pragma unroll
        for (int i = 0; i < 2; i++) {
            int idx = tid + i * NT;                 // 0..511
            int sp = idx >> 8, n = (idx >> 1) & 127, q = idx & 1;
            const __half* s = g_W1T + (size_t)(h * 128 + n) * 512
                              + (p * 2 + sp) * 128 + c * 16 + q * 8;
            CP_ASYNC16(smb + OFF_RING + d * RSLOT + sp * (128 * RS1) + n * RS1 + q * 16, s);
        }
    } else {
        const int c = gi - 32;
        #pragma unroll
        for (int i = 0; i < 2; i++) {
            int idx = tid + i * NT;
            int n = idx >> 2, q = idx & 3;
            const __half* s = g_W2T + (size_t)n * 256 + c * 32 + q * 8;
            CP_ASYNC16(smb + OFF_RING + d * RSLOT + n * RS2 + q * 16, s);
        }
    }
}

// ---------------- main fused MLP ----------------
__global__ __launch_bounds__(NT, 2)
void edge_mlp_2cta(const float* __restrict__ node,
                   const int*   __restrict__ src,
                   const int*   __restrict__ dst,
                   const float* __restrict__ b1,
                   const float* __restrict__ b2,
                   const float* __restrict__ W3,
                   const float* __restrict__ b3,
                   float* __restrict__ out, int E)
{
    extern __shared__ char smc[];
    const uint32_t smb = smem_u32(smc);
    float* smf = (float*)smc;

    const int tid = threadIdx.x;
    const int lane = tid & 31;
    const int g = lane >> 2, t = lane & 3;
    const int wid = tid >> 5;
    const int wm = wid >> 2, wn = wid & 3;      // warp grid 2(M:32 rows) x 4(N:32 cols)
    const int e0 = blockIdx.x * TE;
    const int nedge = min(TE, E - e0);

    issue_chunk(smb, tid, 0);
    CP_COMMIT();

    // ---- gather h_i/h_j -> f16 smem (one RN rounding) ----
    #pragma unroll 4
    for (int i = 0; i < 8; i++) {
        int idx = tid + i * NT;                  // 64 rows x 32 col4-groups
        int m = idx >> 5, c4 = idx & 31;
        int e = min(e0 + m, E - 1);
        int si = src[e], di = dst[e];
        float4 vi = ((const float4*)node)[(size_t)si * 32 + c4];
        float4 vj = ((const float4*)node)[(size_t)di * 32 + c4];
        *(uint2*)(smc + OFF_HI + m * STRH + c4 * 8) =
            make_uint2(f2h2(vi.x, vi.y), f2h2(vi.z, vi.w));
        *(uint2*)(smc + OFF_HJ + m * STRH + c4 * 8) =
            make_uint2(f2h2(vj.x, vj.y), f2h2(vj.z, vj.w));
    }
    for (int i = tid; i < 256; i += NT) smf[OFF_B1 / 4 + i] = b1[i];
    for (int i = tid; i < 128; i += NT) smf[OFF_B2 / 4 + i] = b2[i];
    for (int i = tid; i < 256; i += NT) smf[OFF_W3 / 4 + i] = W3[i];
    if (tid < 2) smf[OFF_B3 / 4 + tid] = b3[tid];
    __syncthreads();

    // ---- per-lane ldmatrix bases ----
    const int aRow = lane & 15;
    const int aKoff = ((lane >> 4) << 3) * 2;   // bytes
    const uint32_t hiBase = smb + OFF_HI + (wm * 32 + aRow) * STRH + aKoff;
    const uint32_t hjBase = smb + OFF_HJ + (wm * 32 + aRow) * STRH + aKoff;
    const uint32_t xBase  = smb + OFF_X1 + (wm * 32 + aRow) * STRX + aKoff;
    const int nl = ((lane >> 4) << 3) + (lane & 7);
    const uint32_t bOff = (lane & 8) ? 16u : 0u;   // bytes

    // layer-2 accumulators (persist), init with b2
    float accL2[2][4][4];
    #pragma unroll
    for (int mt = 0; mt < 2; mt++)
        #pragma unroll
        for (int nt = 0; nt < 4; nt++) {
            int col = wn * 32 + nt * 8 + 2 * t;
            float v0 = smf[OFF_B2 / 4 + col], v1 = smf[OFF_B2 / 4 + col + 1];
            accL2[mt][nt][0] = v0; accL2[mt][nt][1] = v1;
            accL2[mt][nt][2] = v0; accL2[mt][nt][3] = v1;
        }

    int gi = 0;
    // ================= layer 1 (two n-halves) =================
    for (int h = 0; h < 2; h++) {
        float accL1[2][4][4];
        #pragma unroll
        for (int mt = 0; mt < 2; mt++)
            #pragma unroll
            for (int nt = 0; nt < 4; nt++) {
                int col = h * 128 + wn * 32 + nt * 8 + 2 * t;
                float v0 = smf[OFF_B1 / 4 + col], v1 = smf[OFF_B1 / 4 + col + 1];
                accL1[mt][nt][0] = v0; accL1[mt][nt][1] = v1;
                accL1[mt][nt][2] = v0; accL1[mt][nt][3] = v1;
            }

        uint32_t fi[2][4], fj[2][4];
        for (int c = 0; c < 8; c++) {
            #pragma unroll
            for (int p = 0; p < 2; p++, gi++) {
                if (gi < 39) { issue_chunk(smb, tid, gi + 1); CP_COMMIT(); CP_WAIT(1); }
                else         { CP_WAIT(0); }
                __syncthreads();
                const int d = gi & 1;

                if (p == 0) {   // load hi/hj frags for this k-window (reused by p=1)
                    #pragma unroll
                    for (int mt = 0; mt < 2; mt++) {
                        ldm4(fi[mt], hiBase + mt * (16 * STRH) + c * 32);
                        ldm4(fj[mt], hjBase + mt * (16 * STRH) + c * 32);
                    }
                }
                #pragma unroll
                for (int sp = 0; sp < 2; sp++) {
                    uint32_t aF[2][4];
                    #pragma unroll
                    for (int mt = 0; mt < 2; mt++)
                        #pragma unroll
                        for (int x = 0; x < 4; x++) {
                            if (p == 0) aF[mt][x] = sp ? fj[mt][x] : fi[mt][x];
                            else aF[mt][x] = sp ? hmul2u(fi[mt][x], fj[mt][x])
                                                : habs_sub2(fi[mt][x], fj[mt][x]);
                        }
                    uint32_t bF[2][4];
                    const uint32_t bB = smb + OFF_RING + d * RSLOT + sp * (128 * RS1)
                                        + nl * RS1 + bOff;
                    #pragma unroll
                    for (int np = 0; np < 2; np++)
                        ldm4(bF[np], bB + (wn * 32 + np * 16) * RS1);
                    #pragma unroll
                    for (int mt = 0; mt < 2; mt++) {
                        mma16(accL1[mt][0], aF[mt], bF[0][0], bF[0][1]);
                        mma16(accL1[mt][1], aF[mt], bF[0][2], bF[0][3]);
                        mma16(accL1[mt][2], aF[mt], bF[1][0], bF[1][1]);
                        mma16(accL1[mt][3], aF[mt], bF[1][2], bF[1][3]);
                    }
                }
                __syncthreads();
            }
        }

        // x1 = f16x2(relu(acc)) -> smem
        #pragma unroll
        for (int mt = 0; mt < 2; mt++) {
            int r = wm * 32 + mt * 16 + g;
            #pragma unroll
            for (int nt = 0; nt < 4; nt++) {
                int col = h * 128 + wn * 32 + nt * 8 + 2 * t;
                float* A = accL1[mt][nt];
                *(uint32_t*)(smc + OFF_X1 + r * STRX + col * 2) =
                    f2h2(fmaxf(A[0], 0.f), fmaxf(A[1], 0.f));
                *(uint32_t*)(smc + OFF_X1 + (r + 8) * STRX + col * 2) =
                    f2h2(fmaxf(A[2], 0.f), fmaxf(A[3], 0.f));
            }
        }
    }

    // ================= layer 2 (K=256, 8 chunks of 32k) =================
    for (int c = 0; c < 8; c++, gi++) {
        if (gi < 39) { issue_chunk(smb, tid, gi + 1); CP_COMMIT(); CP_WAIT(1); }
        else         { CP_WAIT(0); }
        __syncthreads();   // also orders x1 stores before reads
        const int d = gi & 1;

        #pragma unroll
        for (int kt = 0; kt < 2; kt++) {
            uint32_t aF[2][4];
            #pragma unroll
            for (int mt = 0; mt < 2; mt++)
                ldm4(aF[mt], xBase + mt * (16 * STRX) + (c * 32 + kt * 16) * 2);
            uint32_t bF[2][4];
            const uint32_t bB = smb + OFF_RING + d * RSLOT + nl * RS2 + bOff + kt * 32;
            #pragma unroll
            for (int np = 0; np < 2; np++)
                ldm4(bF[np], bB + (wn * 32 + np * 16) * RS2);
            #pragma unroll
            for (int mt = 0; mt < 2; mt++) {
                mma16(accL2[mt][0], aF[mt], bF[0][0], bF[0][1]);
                mma16(accL2[mt][1], aF[mt], bF[0][2], bF[0][3]);
                mma16(accL2[mt][2], aF[mt], bF[1][0], bF[1][1]);
                mma16(accL2[mt][3], aF[mt], bF[1][2], bF[1][3]);
            }
        }
        __syncthreads();
    }

    // ================= layer 3: register relu.W3 + quad shuffle-reduce =================
    float* s_red = (float*)(smc + OFF_RING);   // ring is dead: [64][8] f32
    #pragma unroll
    for (int mt = 0; mt < 2; mt++) {
        int r = wm * 32 + mt * 16 + g;
        float p00 = 0.f, p01 = 0.f, p10 = 0.f, p11 = 0.f;
        #pragma unroll
        for (int nt = 0; nt < 4; nt++) {
            float* A = accL2[mt][nt];
            int col = wn * 32 + nt * 8 + 2 * t;
            float w00 = smf[OFF_W3 / 4 + 2 * col],     w01 = smf[OFF_W3 / 4 + 2 * col + 1];
            float w10 = smf[OFF_W3 / 4 + 2 * col + 2], w11 = smf[OFF_W3 / 4 + 2 * col + 3];
            float x0 = fmaxf(A[0], 0.f), x1v = fmaxf(A[1], 0.f);
            float x2v = fmaxf(A[2], 0.f), x3v = fmaxf(A[3], 0.f);
            p00 += x0 * w00 + x1v * w10;
            p01 += x0 * w01 + x1v * w11;
            p10 += x2v * w00 + x3v * w10;
            p11 += x2v * w01 + x3v * w11;
        }
        p00 += __shfl_xor_sync(0xFFFFFFFFu, p00, 1);
        p00 += __shfl_xor_sync(0xFFFFFFFFu, p00, 2);
        p01 += __shfl_xor_sync(0xFFFFFFFFu, p01, 1);
        p01 += __shfl_xor_sync(0xFFFFFFFFu, p01, 2);
        p10 += __shfl_xor_sync(0xFFFFFFFFu, p10, 1);
        p10 += __shfl_xor_sync(0xFFFFFFFFu, p10, 2);
        p11 += __shfl_xor_sync(0xFFFFFFFFu, p11, 1);
        p11 += __shfl_xor_sync(0xFFFFFFFFu, p11, 2);
        if (t == 0) {
            s_red[r * 8 + wn * 2 + 0] = p00;
            s_red[r * 8 + wn * 2 + 1] = p01;
            s_red[(r + 8) * 8 + wn * 2 + 0] = p10;
            s_red[(r + 8) * 8 + wn * 2 + 1] = p11;
        }
    }
    __syncthreads();

    if (tid < 2 * TE) {
        int row = tid >> 1, cc = tid & 1;
        float sum = smf[OFF_B3 / 4 + cc]
                  + s_red[row * 8 + 0 + cc] + s_red[row * 8 + 2 + cc]
                  + s_red[row * 8 + 4 + cc] + s_red[row * 8 + 6 + cc];
        if (row < nedge) out[(size_t)(e0 + row) * 2 + cc] = sum;
    }
}

extern "C" void kernel_launch(void* const* d_in, const int* in_sizes, int n_in,
                              void* d_out, int out_size)
{
    const float* node = (const float*)d_in[0];
    const int*   src  = (const int*)  d_in[1];
    const int*   dst  = (const int*)  d_in[2];
    const float* W1   = (const float*)d_in[3];
    const float* b1   = (const float*)d_in[4];
    const float* W2   = (const float*)d_in[5];
    const float* b2   = (const float*)d_in[6];
    const float* W3   = (const float*)d_in[7];
    const float* b3   = (const float*)d_in[8];
    float* out = (float*)d_out;

    const int E = in_sizes[1];

    {
        int total = 256 * 512 + 128 * 256;
        prep_kernel<<<(total + 255) / 256, 256>>>(W1, W2);
    }

    cudaFuncSetAttribute(edge_mlp_2cta,
                         cudaFuncAttributeMaxDynamicSharedMemorySize, SMEM_BYTES);

    const int grid = (E + TE - 1) / TE;
    edge_mlp_2cta<<<grid, NT, SMEM_BYTES>>>(node, src, dst, b1, b2, W3, b3, out, E);
}

// round 12
// speedup vs baseline: 1.1236x; 1.1230x over previous
#include <cuda_runtime.h>
#include <cuda_fp16.h>
#include <cstdint>

#define TE 128
#define NT 256
#define NNODE_MAX 50000

// Static device scratch (no runtime alloc)
__device__ __half g_W1abT[512 * 128];       // UV weights [n=512][k=128] (U|V)
__device__ __half g_W1T[256 * 256];         // edge L1 (diff|prod) [n=256][k=256]
__device__ __half g_W2T[128 * 256];         // [n=128][k=256]
__device__ __half g_UV[(size_t)NNODE_MAX * 512];  // per-node U|V, f16 (51.2 MB)

// ---------------- helpers ----------------
__device__ __forceinline__ uint32_t smem_u32(const void* p) {
    uint32_t a;
    asm("{ .reg .u64 t; cvta.to.shared.u64 t, %1; cvt.u32.u64 %0, t; }" : "=r"(a) : "l"(p));
    return a;
}
__device__ __forceinline__ uint32_t f2h2(float lo, float hi) {
    uint32_t r;
    asm("cvt.rn.f16x2.f32 %0, %1, %2;" : "=r"(r) : "f"(hi), "f"(lo));
    return r;
}
#define CP_ASYNC16(dst_u32, src_ptr) \
    asm volatile("cp.async.cg.shared.global [%0], [%1], 16;" :: "r"(dst_u32), "l"(src_ptr) : "memory")
#define CP_COMMIT() asm volatile("cp.async.commit_group;" ::: "memory")
#define CP_WAIT(n)  asm volatile("cp.async.wait_group %0;" :: "n"(n) : "memory")

__device__ __forceinline__ void mma16(float* c, const uint32_t* a, uint32_t b0, uint32_t b1) {
    asm volatile(
        "mma.sync.aligned.m16n8k16.row.col.f32.f16.f16.f32 "
        "{%0,%1,%2,%3}, {%4,%5,%6,%7}, {%8,%9}, {%0,%1,%2,%3};"
        : "+f"(c[0]), "+f"(c[1]), "+f"(c[2]), "+f"(c[3])
        : "r"(a[0]), "r"(a[1]), "r"(a[2]), "r"(a[3]), "r"(b0), "r"(b1));
}
__device__ __forceinline__ void ldm4(uint32_t* r, uint32_t addr) {
    asm volatile("ldmatrix.sync.aligned.m8n8.x4.shared.b16 {%0,%1,%2,%3}, [%4];"
                 : "=r"(r[0]), "=r"(r[1]), "=r"(r[2]), "=r"(r[3]) : "r"(addr));
}
__device__ __forceinline__ uint32_t habs_sub2(uint32_t a, uint32_t b) {
    __half2 r = __habs2(__hsub2(*(__half2*)&a, *(__half2*)&b));
    return *(uint32_t*)&r;
}
__device__ __forceinline__ uint32_t hmul2u(uint32_t a, uint32_t b) {
    __half2 r = __hmul2(*(__half2*)&a, *(__half2*)&b);
    return *(uint32_t*)&r;
}

// ---------------- smem layout (BYTE offsets), edge kernel ----------------
#define STRH   272       // [128 rows][128 f16 + 16B pad]
#define STRX   528       // x1 [128 rows][256 f16 + 16B pad]
#define WBLK   34816     // one weight block: [128 n][STRH]
#define OFF_HI 0
#define OFF_HJ 34816
#define OFF_W  69632     // 2 x WBLK
#define OFF_X1 139264    // 67,584
#define OFF_SRC 206848   // int[128]
#define OFF_DST 207360   // int[128]
#define OFF_B2  207872   // f32[128]
#define OFF_W3  208384   // f32[256]
#define OFF_B3  209408   // f32[2]
#define SMEM_BYTES 209416

// ---------------- prep 1: round + transpose weights ----------------
__global__ void prep_w(const float* __restrict__ W1, const float* __restrict__ W2) {
    int i = blockIdx.x * blockDim.x + threadIdx.x;
    if (i < 512 * 128) {                       // W1abT [n=512][k=128]
        int n = i >> 7, k = i & 127;
        float v = (n < 256) ? W1[k * 256 + n] : W1[(128 + k) * 256 + (n - 256)];
        g_W1abT[i] = __float2half_rn(v);
    } else if (i < 512 * 128 + 256 * 256) {    // W1T (diff|prod) [n=256][k=256]
        int j = i - 512 * 128;
        int n = j >> 8, k = j & 255;
        float v = (k < 128) ? W1[(256 + k) * 256 + n] : W1[(384 + (k - 128)) * 256 + n];
        g_W1T[j] = __float2half_rn(v);
    } else {
        int j = i - 512 * 128 - 256 * 256;     // W2T [n=128][k=256]
        if (j < 128 * 256) {
            int n = j >> 8, k = j & 255;
            g_W2T[j] = __float2half_rn(W2[k * 128 + n]);
        }
    }
}

// ---------------- prep 2: UV = node @ [W1a|W1b] (+b1 folded into U) ----------------
// grid (ceil(N/128), 4), 256 thr. smem: A[128][STRH] @0, B[128][STRH] @34816, b1 @69632
#define UV_SMEM 70656
__global__ __launch_bounds__(256, 1)
void uv_kernel(const float* __restrict__ node, const float* __restrict__ b1, int nnode) {
    extern __shared__ char smc[];
    const uint32_t smb = smem_u32(smc);
    float* s_b1 = (float*)(smc + 69632);
    const int tid = threadIdx.x, lane = tid & 31;
    const int g = lane >> 2, t = lane & 3;
    const int wid = tid >> 5, wm = wid >> 2, wn = wid & 3;
    const int nb = blockIdx.y;
    const int r0 = blockIdx.x * 128;

    // A: 128 rows x 128 f16  (FIX: i < 16 covers all 128 rows)
    #pragma unroll
    for (int i = 0; i < 16; i++) {
        int idx = tid + i * 256;
        int m = idx >> 5, c4 = idx & 31;
        int nr = min(r0 + m, nnode - 1);
        float4 v = ((const float4*)node)[(size_t)nr * 32 + c4];
        *(uint2*)(smc + m * STRH + c4 * 8) = make_uint2(f2h2(v.x, v.y), f2h2(v.z, v.w));
    }
    // B: 128 rows x 256 B  (FIX: n = idx>>4 in [0,128), q = idx&15 16B chunks)
    #pragma unroll
    for (int i = 0; i < 8; i++) {
        int idx = tid + i * 256;
        int n = idx >> 4, q = idx & 15;
        *(uint4*)(smc + 34816 + n * STRH + q * 16) =
            *(const uint4*)(g_W1abT + (size_t)(nb * 128 + n) * 128 + q * 8);
    }
    for (int i = tid; i < 256; i += 256) s_b1[i] = b1[i];
    __syncthreads();

    float acc[4][4][4];
    #pragma unroll
    for (int mt = 0; mt < 4; mt++)
        #pragma unroll
        for (int nt = 0; nt < 4; nt++) {
            int col = wn * 32 + nt * 8 + 2 * t;
            int gc = nb * 128 + col;
            float v0 = (nb < 2) ? s_b1[gc] : 0.f;
            float v1 = (nb < 2) ? s_b1[gc + 1] : 0.f;
            acc[mt][nt][0] = v0; acc[mt][nt][1] = v1;
            acc[mt][nt][2] = v0; acc[mt][nt][3] = v1;
        }

    const int aRow = lane & 15;
    const int aKoff = ((lane >> 4) << 3) * 2;
    const uint32_t aBase = smb + (wm * 64 + aRow) * STRH + aKoff;
    const int nl = ((lane >> 4) << 3) + (lane & 7);
    const uint32_t bOff = (lane & 8) ? 16u : 0u;

    #pragma unroll
    for (int s = 0; s < 8; s++) {
        uint32_t aF[4][4];
        #pragma unroll
        for (int mt = 0; mt < 4; mt++)
            ldm4(aF[mt], aBase + mt * (16 * STRH) + s * 32);
        uint32_t bF[2][4];
        #pragma unroll
        for (int np = 0; np < 2; np++)
            ldm4(bF[np], smb + 34816 + (wn * 32 + np * 16 + nl) * STRH + bOff + s * 32);
        #pragma unroll
        for (int mt = 0; mt < 4; mt++) {
            mma16(acc[mt][0], aF[mt], bF[0][0], bF[0][1]);
            mma16(acc[mt][1], aF[mt], bF[0][2], bF[0][3]);
            mma16(acc[mt][2], aF[mt], bF[1][0], bF[1][1]);
            mma16(acc[mt][3], aF[mt], bF[1][2], bF[1][3]);
        }
    }

    #pragma unroll
    for (int mt = 0; mt < 4; mt++) {
        int m = wm * 64 + mt * 16 + g;
        #pragma unroll
        for (int nt = 0; nt < 4; nt++) {
            int col = wn * 32 + nt * 8 + 2 * t;
            if (r0 + m < nnode)
                *(uint32_t*)((char*)g_UV + ((size_t)(r0 + m) * 512 + nb * 128 + col) * 2) =
                    f2h2(acc[mt][nt][0], acc[mt][nt][1]);
            if (r0 + m + 8 < nnode)
                *(uint32_t*)((char*)g_UV + ((size_t)(r0 + m + 8) * 512 + nb * 128 + col) * 2) =
                    f2h2(acc[mt][nt][2], acc[mt][nt][3]);
        }
    }
}

// ---------------- edge kernel weight block loads (6 x 32KB) ----------------
// blocks 0-3: L1 (i>>1 selects N-half rows of W1T, i&1 selects k 128-block)
// blocks 4-5: L2 (i-4 selects k 128-block of W2T)
__device__ __forceinline__ void issue_blk(uint32_t smb, int tid, int i) {
    const int d = i & 1;
    const __half* base;
    if (i < 4) base = g_W1T + (size_t)((i >> 1) * 128) * 256 + (i & 1) * 128;
    else       base = g_W2T + (size_t)(i - 4) * 128;
    #pragma unroll
    for (int j = 0; j < 8; j++) {
        int idx = tid + j * NT;           // 0..2047
        int n = idx >> 4, q = idx & 15;
        CP_ASYNC16(smb + OFF_W + d * WBLK + n * STRH + q * 16,
                   base + (size_t)n * 256 + q * 8);
    }
}

// ---------------- main fused edge MLP ----------------
__global__ __launch_bounds__(NT, 1)
void edge_mlp_split(const float* __restrict__ node,
                    const int*   __restrict__ src,
                    const int*   __restrict__ dst,
                    const float* __restrict__ b2,
                    const float* __restrict__ W3,
                    const float* __restrict__ b3,
                    float* __restrict__ out, int E)
{
    extern __shared__ char smc[];
    const uint32_t smb = smem_u32(smc);
    float* smf = (float*)smc;
    int* s_src = (int*)(smc + OFF_SRC);
    int* s_dst = (int*)(smc + OFF_DST);

    const int tid = threadIdx.x, lane = tid & 31;
    const int g = lane >> 2, t = lane & 3;
    const int wid = tid >> 5, wm = wid >> 2, wn = wid & 3;
    const int e0 = blockIdx.x * TE;
    const int nedge = min(TE, E - e0);

    issue_blk(smb, tid, 0); CP_COMMIT();
    issue_blk(smb, tid, 1); CP_COMMIT();

    // gather h_i/h_j -> f16 smem (one rounding); src/dst to smem
    #pragma unroll 4
    for (int i = 0; i < 16; i++) {
        int idx = tid + i * NT;
        int m = idx >> 5, c4 = idx & 31;
        int e = min(e0 + m, E - 1);
        int si = src[e], di = dst[e];
        if (c4 == 0) { s_src[m] = si; s_dst[m] = di; }
        float4 vi = ((const float4*)node)[(size_t)si * 32 + c4];
        float4 vj = ((const float4*)node)[(size_t)di * 32 + c4];
        *(uint2*)(smc + OFF_HI + m * STRH + c4 * 8) =
            make_uint2(f2h2(vi.x, vi.y), f2h2(vi.z, vi.w));
        *(uint2*)(smc + OFF_HJ + m * STRH + c4 * 8) =
            make_uint2(f2h2(vj.x, vj.y), f2h2(vj.z, vj.w));
    }
    for (int i = tid; i < 128; i += NT) smf[OFF_B2 / 4 + i] = b2[i];
    for (int i = tid; i < 256; i += NT) smf[OFF_W3 / 4 + i] = W3[i];
    if (tid < 2) smf[OFF_B3 / 4 + tid] = b3[tid];
    __syncthreads();

    const int aRow = lane & 15;
    const int aKoff = ((lane >> 4) << 3) * 2;
    const uint32_t hiBase = smb + OFF_HI + (wm * 64 + aRow) * STRH + aKoff;
    const uint32_t hjBase = smb + OFF_HJ + (wm * 64 + aRow) * STRH + aKoff;
    const uint32_t xBase  = smb + OFF_X1 + (wm * 64 + aRow) * STRX + aKoff;
    const int nl = ((lane >> 4) << 3) + (lane & 7);
    const uint32_t bOff = (lane & 8) ? 16u : 0u;

    // ================= layer 1: two n-halves, 2 weight-block phases each =================
    for (int h = 0; h < 2; h++) {
        // acc init = UV[src] (U half) + UV[dst] (V half)   [b1 already folded into U]
        float accL1[4][4][4];
        #pragma unroll
        for (int mt = 0; mt < 4; mt++) {
            int r0 = wm * 64 + mt * 16 + g;
            const __half* U0 = g_UV + (size_t)s_src[r0] * 512;
            const __half* V0 = g_UV + (size_t)s_dst[r0] * 512 + 256;
            const __half* U1 = g_UV + (size_t)s_src[r0 + 8] * 512;
            const __half* V1 = g_UV + (size_t)s_dst[r0 + 8] * 512 + 256;
            #pragma unroll
            for (int nt = 0; nt < 4; nt++) {
                int c = h * 128 + wn * 32 + nt * 8 + 2 * t;
                float2 u0 = __half22float2(*(const __half2*)(U0 + c));
                float2 v0 = __half22float2(*(const __half2*)(V0 + c));
                float2 u1 = __half22float2(*(const __half2*)(U1 + c));
                float2 v1 = __half22float2(*(const __half2*)(V1 + c));
                accL1[mt][nt][0] = u0.x + v0.x; accL1[mt][nt][1] = u0.y + v0.y;
                accL1[mt][nt][2] = u1.x + v1.x; accL1[mt][nt][3] = u1.y + v1.y;
            }
        }

        #pragma unroll
        for (int p = 0; p < 2; p++) {
            const int ph = h * 2 + p, d = ph & 1;
            CP_WAIT(1);
            __syncthreads();

            #pragma unroll
            for (int s = 0; s < 8; s++) {
                uint32_t fi[4][4], fj[4][4], aF[4][4];
                #pragma unroll
                for (int mt = 0; mt < 4; mt++) {
                    ldm4(fi[mt], hiBase + mt * (16 * STRH) + s * 32);
                    ldm4(fj[mt], hjBase + mt * (16 * STRH) + s * 32);
                }
                #pragma unroll
                for (int mt = 0; mt < 4; mt++)
                    #pragma unroll
                    for (int x = 0; x < 4; x++)
                        aF[mt][x] = p ? hmul2u(fi[mt][x], fj[mt][x])
                                      : habs_sub2(fi[mt][x], fj[mt][x]);
                uint32_t bF[2][4];
                #pragma unroll
                for (int np = 0; np < 2; np++)
                    ldm4(bF[np], smb + OFF_W + d * WBLK
                                 + (wn * 32 + np * 16 + nl) * STRH + bOff + s * 32);
                #pragma unroll
                for (int mt = 0; mt < 4; mt++) {
                    mma16(accL1[mt][0], aF[mt], bF[0][0], bF[0][1]);
                    mma16(accL1[mt][1], aF[mt], bF[0][2], bF[0][3]);
                    mma16(accL1[mt][2], aF[mt], bF[1][0], bF[1][1]);
                    mma16(accL1[mt][3], aF[mt], bF[1][2], bF[1][3]);
                }
            }
            __syncthreads();
            if (ph + 2 <= 5) { issue_blk(smb, tid, ph + 2); CP_COMMIT(); }
        }

        // x1 = f16(relu(acc)) -> smem
        #pragma unroll
        for (int mt = 0; mt < 4; mt++) {
            int r = wm * 64 + mt * 16 + g;
            #pragma unroll
            for (int nt = 0; nt < 4; nt++) {
                int col = h * 128 + wn * 32 + nt * 8 + 2 * t;
                float* A = accL1[mt][nt];
                *(uint32_t*)(smc + OFF_X1 + r * STRX + col * 2) =
                    f2h2(fmaxf(A[0], 0.f), fmaxf(A[1], 0.f));
                *(uint32_t*)(smc + OFF_X1 + (r + 8) * STRX + col * 2) =
                    f2h2(fmaxf(A[2], 0.f), fmaxf(A[3], 0.f));
            }
        }
    }

    // ================= layer 2: 2 weight-block phases =================
    float accL2[4][4][4];
    #pragma unroll
    for (int mt = 0; mt < 4; mt++)
        #pragma unroll
        for (int nt = 0; nt < 4; nt++) {
            int col = wn * 32 + nt * 8 + 2 * t;
            float v0 = smf[OFF_B2 / 4 + col], v1 = smf[OFF_B2 / 4 + col + 1];
            accL2[mt][nt][0] = v0; accL2[mt][nt][1] = v1;
            accL2[mt][nt][2] = v0; accL2[mt][nt][3] = v1;
        }

    #pragma unroll
    for (int p = 0; p < 2; p++) {
        const int ph = 4 + p, d = ph & 1;
        if (ph < 5) CP_WAIT(1); else CP_WAIT(0);
        __syncthreads();   // also orders x1 stores before reads

        #pragma unroll
        for (int s = 0; s < 8; s++) {
            uint32_t aF[4][4];
            #pragma unroll
            for (int mt = 0; mt < 4; mt++)
                ldm4(aF[mt], xBase + mt * (16 * STRX) + (p * 128 + s * 16) * 2);
            uint32_t bF[2][4];
            #pragma unroll
            for (int np = 0; np < 2; np++)
                ldm4(bF[np], smb + OFF_W + d * WBLK
                             + (wn * 32 + np * 16 + nl) * STRH + bOff + s * 32);
            #pragma unroll
            for (int mt = 0; mt < 4; mt++) {
                mma16(accL2[mt][0], aF[mt], bF[0][0], bF[0][1]);
                mma16(accL2[mt][1], aF[mt], bF[0][2], bF[0][3]);
                mma16(accL2[mt][2], aF[mt], bF[1][0], bF[1][1]);
                mma16(accL2[mt][3], aF[mt], bF[1][2], bF[1][3]);
            }
        }
        __syncthreads();
    }

    // ================= layer 3: register relu.W3 + quad shuffle-reduce =================
    float* s_red = (float*)(smc + OFF_W);   // weight region dead: [128][8] f32
    #pragma unroll
    for (int mt = 0; mt < 4; mt++) {
        int r = wm * 64 + mt * 16 + g;
        float p00 = 0.f, p01 = 0.f, p10 = 0.f, p11 = 0.f;
        #pragma unroll
        for (int nt = 0; nt < 4; nt++) {
            float* A = accL2[mt][nt];
            int col = wn * 32 + nt * 8 + 2 * t;
            float w00 = smf[OFF_W3 / 4 + 2 * col],     w01 = smf[OFF_W3 / 4 + 2 * col + 1];
            float w10 = smf[OFF_W3 / 4 + 2 * col + 2], w11 = smf[OFF_W3 / 4 + 2 * col + 3];
            float x0 = fmaxf(A[0], 0.f), x1v = fmaxf(A[1], 0.f);
            float x2v = fmaxf(A[2], 0.f), x3v = fmaxf(A[3], 0.f);
            p00 += x0 * w00 + x1v * w10;
            p01 += x0 * w01 + x1v * w11;
            p10 += x2v * w00 + x3v * w10;
            p11 += x2v * w01 + x3v * w11;
        }
        p00 += __shfl_xor_sync(0xFFFFFFFFu, p00, 1);
        p00 += __shfl_xor_sync(0xFFFFFFFFu, p00, 2);
        p01 += __shfl_xor_sync(0xFFFFFFFFu, p01, 1);
        p01 += __shfl_xor_sync(0xFFFFFFFFu, p01, 2);
        p10 += __shfl_xor_sync(0xFFFFFFFFu, p10, 1);
        p10 += __shfl_xor_sync(0xFFFFFFFFu, p10, 2);
        p11 += __shfl_xor_sync(0xFFFFFFFFu, p11, 1);
        p11 += __shfl_xor_sync(0xFFFFFFFFu, p11, 2);
        if (t == 0) {
            s_red[r * 8 + wn * 2 + 0] = p00;
            s_red[r * 8 + wn * 2 + 1] = p01;
            s_red[(r + 8) * 8 + wn * 2 + 0] = p10;
            s_red[(r + 8) * 8 + wn * 2 + 1] = p11;
        }
    }
    __syncthreads();

    {
        int row = tid >> 1, cc = tid & 1;
        float sum = smf[OFF_B3 / 4 + cc]
                  + s_red[row * 8 + 0 + cc] + s_red[row * 8 + 2 + cc]
                  + s_red[row * 8 + 4 + cc] + s_red[row * 8 + 6 + cc];
        if (row < nedge) out[(size_t)(e0 + row) * 2 + cc] = sum;
    }
}

extern "C" void kernel_launch(void* const* d_in, const int* in_sizes, int n_in,
                              void* d_out, int out_size)
{
    const float* node = (const float*)d_in[0];
    const int*   src  = (const int*)  d_in[1];
    const int*   dst  = (const int*)  d_in[2];
    const float* W1   = (const float*)d_in[3];
    const float* b1   = (const float*)d_in[4];
    const float* W2   = (const float*)d_in[5];
    const float* b2   = (const float*)d_in[6];
    const float* W3   = (const float*)d_in[7];
    const float* b3   = (const float*)d_in[8];
    float* out = (float*)d_out;

    const int E = in_sizes[1];
    const int nnode = in_sizes[0] / 128;

    {   // prep 1: weight rounding/transpose
        int total = 512 * 128 + 256 * 256 + 128 * 256;
        prep_w<<<(total + 255) / 256, 256>>>(W1, W2);
    }
    {   // prep 2: UV = node @ [W1a|W1b] + [b1|0]
        cudaFuncSetAttribute(uv_kernel,
                             cudaFuncAttributeMaxDynamicSharedMemorySize, UV_SMEM);
        dim3 grid((nnode + 127) / 128, 4);
        uv_kernel<<<grid, 256, UV_SMEM>>>(node, b1, nnode);
    }

    cudaFuncSetAttribute(edge_mlp_split,
                         cudaFuncAttributeMaxDynamicSharedMemorySize, SMEM_BYTES);
    const int grid = (E + TE - 1) / TE;
    edge_mlp_split<<<grid, NT, SMEM_BYTES>>>(node, src, dst, b2, W3, b3, out, E);
}